// round 5
// baseline (speedup 1.0000x reference)
#include <cuda_runtime.h>

#define NN 4096
#define DIM 64
#define INF_V 1e10f
#define NBLK 32           // 128 rows per DP block (one warp, 4 rows/lane)
#define NTILE 1024        // tile-columns (4 cols each)
#define LOG2E 1.4426950408889634f
#define LN2   0.6931471805599453f

// Scratch (static __device__ arrays: allocation-free per harness rules)
__device__ float g_D[(size_t)NN * NN];    // cost matrix, PRE-SCALED by log2(e)
__device__ float g_xn[NN];
__device__ float g_yn[NN];
__device__ float g_bndR[NBLK][NN];        // boundary pairs: ref
__device__ float g_bndS[NBLK][NN];        // boundary pairs: scale
__device__ int   g_prog[NBLK];            // tiles published per block

// ---------------- norms ----------------
__global__ void norms_kernel(const float* __restrict__ x, const float* __restrict__ y) {
    int w = (blockIdx.x * blockDim.x + threadIdx.x) >> 5;
    int lane = threadIdx.x & 31;
    if (w >= 2 * NN) return;
    const float* src = (w < NN) ? x : y;
    int row = (w < NN) ? w : w - NN;
    float a = src[row * DIM + lane];
    float b = src[row * DIM + 32 + lane];
    float s = a * a + b * b;
    #pragma unroll
    for (int o = 16; o; o >>= 1) s += __shfl_xor_sync(0xffffffffu, s, o);
    if (lane == 0) { if (w < NN) g_xn[row] = s; else g_yn[row] = s; }
}

// ---------------- D2 = (|x|^2 + |y|^2 - 2 x.y) * log2(e) ----------------
__global__ void dmat_kernel(const float* __restrict__ x, const float* __restrict__ y) {
    __shared__ float xs[64][65];
    __shared__ float ys[64][65];
    int tx = threadIdx.x, ty = threadIdx.y;
    int tid = ty * 16 + tx;
    int rb = blockIdx.y * 64, cb = blockIdx.x * 64;

    for (int i = tid; i < 64 * 64; i += 256) {
        int rr = i >> 6, kk = i & 63;
        xs[rr][kk] = x[(rb + rr) * DIM + kk];
        ys[rr][kk] = y[(cb + rr) * DIM + kk];
    }
    __syncthreads();

    float acc[4][4] = {};
    #pragma unroll
    for (int k = 0; k < 64; k++) {
        float xv[4], yv[4];
        #pragma unroll
        for (int i = 0; i < 4; i++) xv[i] = xs[ty + 16 * i][k];
        #pragma unroll
        for (int j = 0; j < 4; j++) yv[j] = ys[tx + 16 * j][k];
        #pragma unroll
        for (int i = 0; i < 4; i++)
            #pragma unroll
            for (int j = 0; j < 4; j++)
                acc[i][j] += xv[i] * yv[j];
    }

    #pragma unroll
    for (int i = 0; i < 4; i++) {
        int r = rb + ty + 16 * i;
        float xnr = g_xn[r];
        #pragma unroll
        for (int j = 0; j < 4; j++) {
            int c = cb + tx + 16 * j;
            g_D[(size_t)r * NN + c] = (xnr + g_yn[c] - 2.0f * acc[i][j]) * LOG2E;
        }
    }
}

// ---------------- reset progress flags ----------------
__global__ void init_kernel() {
    if (threadIdx.x < NBLK) g_prog[threadIdx.x] = 0;
}

// ---------------- DP wavefront: exp-domain (ref,scale) pairs ----------------
__device__ __forceinline__ int ld_acq(const int* p) {
    int v;
    asm volatile("ld.acquire.gpu.u32 %0, [%1];" : "=r"(v) : "l"(p) : "memory");
    return v;
}
__device__ __forceinline__ void st_rel(int* p, int v) {
    asm volatile("st.release.gpu.u32 [%0], %1;" :: "l"(p), "r"(v) : "memory");
}
__device__ __forceinline__ float ex2(float x) {
    float r; asm("ex2.approx.f32 %0, %1;" : "=f"(r) : "f"(x)); return r;
}

// value = r - log2(s).  Cell: exact logsumexp with reference m = min of refs.
#define CELL2(rO, sO, rU, sU, rD, sD, rL, sL, cost) do {               \
    float m_ = fminf(fminf((rU), (rD)), (rL));                         \
    float eu_ = ex2(m_ - (rU));                                        \
    float ed_ = ex2(m_ - (rD));                                        \
    float el_ = ex2(m_ - (rL));                                        \
    (sO) = fmaf((sU), eu_, fmaf((sD), ed_, (sL) * el_));               \
    (rO) = (cost) + m_;                                                \
} while (0)

// exact power-of-2 renormalization: fold exponent of s into r
#define NORM(r, s) do {                                                \
    int e_ = (__float_as_int(s) >> 23) - 127;                          \
    (s) = __int_as_float(__float_as_int(s) - (e_ << 23));              \
    (r) += (float)e_;                                                  \
} while (0)

__global__ void __launch_bounds__(32, 1) dp_kernel(float* __restrict__ out) {
    __shared__ float topbR[17];
    __shared__ float topbS[17];

    const int b = blockIdx.x;
    const int L = threadIdx.x;
    const int row0 = b * 128 + 4 * L;
    const float4* __restrict__ Dr0 = (const float4*)(g_D + (size_t)(row0 + 0) * NN);
    const float4* __restrict__ Dr1 = (const float4*)(g_D + (size_t)(row0 + 1) * NN);
    const float4* __restrict__ Dr2 = (const float4*)(g_D + (size_t)(row0 + 2) * NN);
    const float4* __restrict__ Dr3 = (const float4*)(g_D + (size_t)(row0 + 3) * NN);
    float* mybndR = g_bndR[b];
    float* mybndS = g_bndS[b];
    const float* upbndR = (b > 0) ? g_bndR[b - 1] : (const float*)0;
    const float* upbndS = (b > 0) ? g_bndS[b - 1] : (const float*)0;

    float lftR[4] = {INF_V, INF_V, INF_V, INF_V};
    float lftS[4] = {1.0f, 1.0f, 1.0f, 1.0f};
    float botR0 = INF_V, botR1 = INF_V, botR2 = INF_V, botR3 = INF_V;
    float botS0 = 1.0f,  botS1 = 1.0f,  botS2 = 1.0f,  botS3 = 1.0f;
    float dgR = INF_V, dgS = 1.0f;

    float4 c0 = __ldg(Dr0), c1 = __ldg(Dr1), c2 = __ldg(Dr2), c3 = __ldg(Dr3);

    const int TT = NTILE + 31;
    #pragma unroll 1
    for (int tau = 0; tau < TT; tau++) {
        const int j = tau - L;

        // ---- stage boundary pair window every 4 tiles ----
        if (b > 0 && tau < NTILE && (tau & 3) == 0) {
            if (L == 0) { while (ld_acq(&g_prog[b - 1]) < tau + 4) { } }
            __syncwarp();
            if (L < 17) {
                int col = 4 * tau - 1 + L;
                if (col >= 0) {
                    topbR[L] = __ldcg(&upbndR[col]);
                    topbS[L] = __ldcg(&upbndS[col]);
                } else { topbR[L] = INF_V; topbS[L] = 1.0f; }
            }
            __syncwarp();
        }

        // ---- prefetch next tile costs ----
        int jn = j + 1; if (jn < 0) jn = 0; if (jn > NTILE - 1) jn = NTILE - 1;
        float4 p0 = __ldg(Dr0 + jn);
        float4 p1 = __ldg(Dr1 + jn);
        float4 p2 = __ldg(Dr2 + jn);
        float4 p3 = __ldg(Dr3 + jn);

        // ---- top handoff: neighbor's bottom-row pairs from previous step ----
        float tR0 = __shfl_up_sync(0xffffffffu, botR0, 1);
        float tR1 = __shfl_up_sync(0xffffffffu, botR1, 1);
        float tR2 = __shfl_up_sync(0xffffffffu, botR2, 1);
        float tR3 = __shfl_up_sync(0xffffffffu, botR3, 1);
        float tS0 = __shfl_up_sync(0xffffffffu, botS0, 1);
        float tS1 = __shfl_up_sync(0xffffffffu, botS1, 1);
        float tS2 = __shfl_up_sync(0xffffffffu, botS2, 1);
        float tS3 = __shfl_up_sync(0xffffffffu, botS3, 1);
        if (L == 0) {
            if (b == 0) {
                tR0 = tR1 = tR2 = tR3 = INF_V;
                tS0 = tS1 = tS2 = tS3 = 1.0f;
                dgR = (tau == 0) ? 0.0f : INF_V; dgS = 1.0f;
            } else {
                int p = (tau & 3) * 4;
                dgR = topbR[p];     dgS = topbS[p];
                tR0 = topbR[p + 1]; tS0 = topbS[p + 1];
                tR1 = topbR[p + 2]; tS1 = topbS[p + 2];
                tR2 = topbR[p + 3]; tS2 = topbS[p + 3];
                tR3 = topbR[p + 4]; tS3 = topbS[p + 4];
            }
        }
        if (j == 0 && L > 0) { dgR = INF_V; dgS = 1.0f; }

        if (j >= 0 && j < NTILE) {
            float uR0 = tR0, uR1 = tR1, uR2 = tR2, uR3 = tR3;
            float uS0 = tS0, uS1 = tS1, uS2 = tS2, uS3 = tS3;
            float nlR[4], nlS[4];
            {   // row 0
                float dR = dgR, dS = dgS, lR = lftR[0], lS = lftS[0];
                float nR0, nS0, nR1, nS1, nR2, nS2, nR3, nS3;
                CELL2(nR0, nS0, uR0, uS0, dR, dS, lR, lS, c0.x); dR = uR0; dS = uS0; lR = nR0; lS = nS0;
                CELL2(nR1, nS1, uR1, uS1, dR, dS, lR, lS, c0.y); dR = uR1; dS = uS1; lR = nR1; lS = nS1;
                CELL2(nR2, nS2, uR2, uS2, dR, dS, lR, lS, c0.z); dR = uR2; dS = uS2; lR = nR2; lS = nS2;
                CELL2(nR3, nS3, uR3, uS3, dR, dS, lR, lS, c0.w);
                nlR[0] = nR3; nlS[0] = nS3;
                uR0 = nR0; uS0 = nS0; uR1 = nR1; uS1 = nS1;
                uR2 = nR2; uS2 = nS2; uR3 = nR3; uS3 = nS3;
            }
            {   // row 1 (diag at k=0 is OLD lft[0])
                float dR = lftR[0], dS = lftS[0], lR = lftR[1], lS = lftS[1];
                float nR0, nS0, nR1, nS1, nR2, nS2, nR3, nS3;
                CELL2(nR0, nS0, uR0, uS0, dR, dS, lR, lS, c1.x); dR = uR0; dS = uS0; lR = nR0; lS = nS0;
                CELL2(nR1, nS1, uR1, uS1, dR, dS, lR, lS, c1.y); dR = uR1; dS = uS1; lR = nR1; lS = nS1;
                CELL2(nR2, nS2, uR2, uS2, dR, dS, lR, lS, c1.z); dR = uR2; dS = uS2; lR = nR2; lS = nS2;
                CELL2(nR3, nS3, uR3, uS3, dR, dS, lR, lS, c1.w);
                nlR[1] = nR3; nlS[1] = nS3;
                uR0 = nR0; uS0 = nS0; uR1 = nR1; uS1 = nS1;
                uR2 = nR2; uS2 = nS2; uR3 = nR3; uS3 = nS3;
            }
            {   // row 2
                float dR = lftR[1], dS = lftS[1], lR = lftR[2], lS = lftS[2];
                float nR0, nS0, nR1, nS1, nR2, nS2, nR3, nS3;
                CELL2(nR0, nS0, uR0, uS0, dR, dS, lR, lS, c2.x); dR = uR0; dS = uS0; lR = nR0; lS = nS0;
                CELL2(nR1, nS1, uR1, uS1, dR, dS, lR, lS, c2.y); dR = uR1; dS = uS1; lR = nR1; lS = nS1;
                CELL2(nR2, nS2, uR2, uS2, dR, dS, lR, lS, c2.z); dR = uR2; dS = uS2; lR = nR2; lS = nS2;
                CELL2(nR3, nS3, uR3, uS3, dR, dS, lR, lS, c2.w);
                nlR[2] = nR3; nlS[2] = nS3;
                uR0 = nR0; uS0 = nS0; uR1 = nR1; uS1 = nS1;
                uR2 = nR2; uS2 = nS2; uR3 = nR3; uS3 = nS3;
            }
            {   // row 3
                float dR = lftR[2], dS = lftS[2], lR = lftR[3], lS = lftS[3];
                float nR0, nS0, nR1, nS1, nR2, nS2, nR3, nS3;
                CELL2(nR0, nS0, uR0, uS0, dR, dS, lR, lS, c3.x); dR = uR0; dS = uS0; lR = nR0; lS = nS0;
                CELL2(nR1, nS1, uR1, uS1, dR, dS, lR, lS, c3.y); dR = uR1; dS = uS1; lR = nR1; lS = nS1;
                CELL2(nR2, nS2, uR2, uS2, dR, dS, lR, lS, c3.z); dR = uR2; dS = uS2; lR = nR2; lS = nS2;
                CELL2(nR3, nS3, uR3, uS3, dR, dS, lR, lS, c3.w);
                nlR[3] = nR3; nlS[3] = nS3;
                uR0 = nR0; uS0 = nS0; uR1 = nR1; uS1 = nS1;
                uR2 = nR2; uS2 = nS2; uR3 = nR3; uS3 = nS3;
            }
            lftR[0] = nlR[0]; lftR[1] = nlR[1]; lftR[2] = nlR[2]; lftR[3] = nlR[3];
            lftS[0] = nlS[0]; lftS[1] = nlS[1]; lftS[2] = nlS[2]; lftS[3] = nlS[3];
            botR0 = uR0; botR1 = uR1; botR2 = uR2; botR3 = uR3;
            botS0 = uS0; botS1 = uS1; botS2 = uS2; botS3 = uS3;

            if (L == 31) {
                *(float4*)&mybndR[4 * j] = make_float4(botR0, botR1, botR2, botR3);
                *(float4*)&mybndS[4 * j] = make_float4(botS0, botS1, botS2, botS3);
                if ((j & 3) == 3 && b < NBLK - 1)
                    st_rel(&g_prog[b], j + 1);
            }
        }
        dgR = tR3; dgS = tS3;

        // ---- periodic exact renormalization (overflow safety) ----
        if ((tau & 3) == 3) {
            NORM(lftR[0], lftS[0]); NORM(lftR[1], lftS[1]);
            NORM(lftR[2], lftS[2]); NORM(lftR[3], lftS[3]);
            NORM(botR0, botS0); NORM(botR1, botS1);
            NORM(botR2, botS2); NORM(botR3, botS3);
        }

        c0 = p0; c1 = p1; c2 = p2; c3 = p3;
    }

    if (b == NBLK - 1 && L == 31)
        out[0] = (lftR[3] - log2f(lftS[3])) * LN2;   // dp[4096][4096]
}

extern "C" void kernel_launch(void* const* d_in, const int* in_sizes, int n_in,
                              void* d_out, int out_size) {
    const float* x = (const float*)d_in[0];
    const float* y = (const float*)d_in[1];
    float* out = (float*)d_out;

    norms_kernel<<<(2 * NN * 32) / 256, 256>>>(x, y);
    dim3 gD(NN / 64, NN / 64);
    dim3 bD(16, 16);
    dmat_kernel<<<gD, bD>>>(x, y);
    init_kernel<<<1, NBLK>>>();
    dp_kernel<<<NBLK, 32>>>(out);
}